// round 16
// baseline (speedup 1.0000x reference)
#include <cuda_runtime.h>
#include <cstdint>

#define NB 8192
#define KD 4096
#define NF 256
#define RPC 64          // rows per CTA
#define NCTA (NB/RPC)   // 128
#define NTHR 256
#define MAXIT 500
#define TOLSQ 1e-4f     // (0.01)^2
#define LRATE 0.1f
#define SHRINKV 0.25f

// ---------------- device scratch (no allocs allowed) ----------------
__device__ float g_G[NF * NF];          // Gram matrix, diag zeroed
__device__ float g_part[2][NCTA];       // per-CTA partial sum of du^2, double buffered
__device__ unsigned g_cnt;              // monotonic grid-barrier counter

// ---------------- helpers ----------------
__device__ __forceinline__ unsigned long long pk2(float lo, float hi) {
    unsigned long long r;
    asm("mov.b64 %0, {%1, %2};" : "=l"(r) : "f"(lo), "f"(hi));
    return r;
}
__device__ __forceinline__ void upk2(unsigned long long v, float& lo, float& hi) {
    asm("mov.b64 {%0, %1}, %2;" : "=f"(lo), "=f"(hi) : "l"(v));
}
// packed fp32x2 FMA: d = a*b + d (full-rate fp32 path on sm_103a)
__device__ __forceinline__ void fma2(unsigned long long& d, unsigned long long a, unsigned long long b) {
    asm("fma.rn.f32x2 %0, %1, %2, %0;" : "+l"(d) : "l"(a), "l"(b));
}
__device__ __forceinline__ uint32_t s2u(const void* p) {
    return (uint32_t)__cvta_generic_to_shared(p);
}
__device__ __forceinline__ void cpasync16(uint32_t saddr, const void* g) {
    asm volatile("cp.async.cg.shared.global [%0], [%1], 16;" :: "r"(saddr), "l"(g));
}
#define CP_COMMIT() asm volatile("cp.async.commit_group;")

// ---------------- init: reset barrier counter (every replay) ----------------
__global__ void init_kernel() {
    if (threadIdx.x == 0) g_cnt = 0u;
}

// ---------------- Gram: G = phi^T phi, zero diagonal ----------------
__global__ void gram_kernel(const float* __restrict__ phi) {
    __shared__ float si[64][17];
    __shared__ float sj[64][17];
    const int I0 = blockIdx.y * 16, J0 = blockIdx.x * 16;
    const int t = threadIdx.x;
    const int ti = t & 15, tj = t >> 4;
    float acc = 0.f;
    for (int k0 = 0; k0 < KD; k0 += 64) {
        __syncthreads();
#pragma unroll
        for (int p = 0; p < 4; p++) {
            int kk = p * 16 + tj;
            si[kk][ti] = phi[(size_t)(k0 + kk) * NF + I0 + ti];
            sj[kk][ti] = phi[(size_t)(k0 + kk) * NF + J0 + ti];
        }
        __syncthreads();
#pragma unroll 16
        for (int kk = 0; kk < 64; kk++) acc += si[kk][tj] * sj[kk][ti];
    }
    const int gi = I0 + tj, gj = J0 + ti;
    g_G[gi * NF + gj] = (gi == gj) ? 0.f : acc;
}

// ---------------- persistent LCA kernel ----------------
// 128 CTAs x 256 threads, 1 CTA/SM (all resident -> grid barrier safe).
// Column mapping (conflict-free): thread (tx,ty) owns packed fp32-pairs
//   pc = tx + 32*ci (ci=0..3), i.e. float cols 2*pc, 2*pc+1.
// SPARSE inner loop: warp ty owns rows r0p..r0p+7 entirely (lanes = columns),
// so the per-row nonzero activation list is warp-uniform. Each tile, the warp
// ballot-compacts its rows' act>0 entries into (act, k_float_offset) pairs
// (padded to even count with exact-zero terms); the GEMM iterates only those.
// Skipped terms are fma(0,g)=identity -> accumulator bits identical to dense.
// smem (dynamic 192KB): u[64][256] | excite[64][256] | staging 16384 floats
__global__ void __launch_bounds__(NTHR, 1)
lca_kernel(const float* __restrict__ images, const float* __restrict__ phi,
           float* __restrict__ out) {
    extern __shared__ float sm[];
    float* s_u  = sm;                 // 16384 floats
    float* s_ex = sm + RPC * NF;      // 16384 floats
    float* s_st = sm + 2 * RPC * NF;  // 16384 floats staging (G tiles / prologue tiles)
    __shared__ float2 s_cl[RPC * 34]; // compacted (act, koff) lists, 34 slots/row (17KB)
    __shared__ int    s_nn[RPC];      // padded-even list length per row
    __shared__ float  s_red[40];

    const int tid = threadIdx.x;
    const int tx = tid & 31, ty = tid >> 5;
    const int r0p = ty * 8;       // 8 rows per thread (and per warp)
    const int cta = blockIdx.x;
    const int row0 = cta * RPC;

    unsigned long long acc[8][4];

    // ================= prologue: excite = images[rows] @ phi =================
    {
        float* s_img = s_st;          // [64][16]
        float* s_phi = s_st + 1024;   // [16][256]
#pragma unroll
        for (int ri = 0; ri < 8; ri++)
#pragma unroll
            for (int ci = 0; ci < 4; ci++) acc[ri][ci] = 0ull;

        for (int kt = 0; kt < KD; kt += 16) {
            __syncthreads();
            {   // img tile 64x16
                int r = tid >> 2, c = (tid & 3) * 4;
                *reinterpret_cast<float4*>(s_img + r * 16 + c) =
                    *reinterpret_cast<const float4*>(images + (size_t)(row0 + r) * KD + kt + c);
            }
            {   // phi tile 16x256 = 4096 contiguous floats
                const float* src = phi + (size_t)kt * NF;
#pragma unroll
                for (int i = 0; i < 4; i++) {
                    int off = i * 1024 + tid * 4;
                    *reinterpret_cast<float4*>(s_phi + off) =
                        *reinterpret_cast<const float4*>(src + off);
                }
            }
            __syncthreads();
#pragma unroll
            for (int kp = 0; kp < 8; kp++) {   // 2 kk per step
                float2 ap[8];
#pragma unroll
                for (int ri = 0; ri < 8; ri++)
                    ap[ri] = *reinterpret_cast<const float2*>(
                        s_img + (r0p + ri) * 16 + kp * 2);
                const unsigned long long* gp0 =
                    reinterpret_cast<const unsigned long long*>(s_phi + (2 * kp) * NF);
                const unsigned long long* gp1 =
                    reinterpret_cast<const unsigned long long*>(s_phi + (2 * kp + 1) * NF);
#pragma unroll
                for (int ri = 0; ri < 8; ri++) {
                    unsigned long long a2 = pk2(ap[ri].x, ap[ri].x);
                    fma2(acc[ri][0], a2, gp0[tx]);
                    fma2(acc[ri][1], a2, gp0[tx + 32]);
                    fma2(acc[ri][2], a2, gp0[tx + 64]);
                    fma2(acc[ri][3], a2, gp0[tx + 96]);
                }
#pragma unroll
                for (int ri = 0; ri < 8; ri++) {
                    unsigned long long a2 = pk2(ap[ri].y, ap[ri].y);
                    fma2(acc[ri][0], a2, gp1[tx]);
                    fma2(acc[ri][1], a2, gp1[tx + 32]);
                    fma2(acc[ri][2], a2, gp1[tx + 64]);
                    fma2(acc[ri][3], a2, gp1[tx + 96]);
                }
            }
        }
        __syncthreads();
#pragma unroll
        for (int ri = 0; ri < 8; ri++)
#pragma unroll
            for (int ci = 0; ci < 4; ci++) {
                float lo, hi; upk2(acc[ri][ci], lo, hi);
                int base = (r0p + ri) * NF + (tx + 32 * ci) * 2;
                s_ex[base] = lo; s_ex[base + 1] = hi;
            }
        for (int i = tid; i < RPC * NF; i += NTHR) s_u[i] = 0.f;
        __syncthreads();
    }

    // ================= fixed-point iterations =================
    for (int it = 0; it < MAXIT; ++it) {
#pragma unroll
        for (int ri = 0; ri < 8; ri++)
#pragma unroll
            for (int ci = 0; ci < 4; ci++) acc[ri][ci] = 0ull;

        if (it > 0) {   // it==0: act==T(0)==0 -> acc stays 0, skip the GEMM
            // prefetch G tile 0 (32 rows x 256 cols, 32KB)
            {
                uint32_t dst = s2u(s_st);
                const float* src = g_G;
#pragma unroll
                for (int i = 0; i < 8; i++) {
                    int off = i * 1024 + tid * 4;
                    cpasync16(dst + off * 4, src + off);
                }
                CP_COMMIT();
            }

            for (int t = 0; t < 8; t++) {
                // ---- ballot-compact this warp's 8 rows for k in [t*32,t*32+32) ----
                {
                    int kt = t * 32;
#pragma unroll
                    for (int rr = 0; rr < 8; rr++) {
                        int r = r0p + rr;
                        float u = s_u[r * NF + kt + tx];   // lane tx -> local k = tx
                        bool pred = u > SHRINKV;
                        unsigned mask = __ballot_sync(0xffffffffu, pred);
                        int pos = __popc(mask & ((1u << tx) - 1u));
                        int cnt = __popc(mask);
                        float2* cl = s_cl + r * 34;
                        if (pred) cl[pos] = make_float2(u, __int_as_float(tx * NF));
                        if (tx == cnt && (cnt & 1)) cl[cnt] = make_float2(0.f, 0.f);
                        if (tx == 0) s_nn[r] = (cnt + 1) & ~1;
                    }
                }
                if (t < 7) {
                    uint32_t dst = s2u(s_st + ((t + 1) & 1) * 8192);
                    const float* src = g_G + (t + 1) * 8192;
#pragma unroll
                    for (int i = 0; i < 8; i++) {
                        int off = i * 1024 + tid * 4;
                        cpasync16(dst + off * 4, src + off);
                    }
                    CP_COMMIT();
                    asm volatile("cp.async.wait_group 1;");
                } else {
                    asm volatile("cp.async.wait_group 0;");
                }
                __syncthreads();   // G tile ready; also orders list writes->reads

                const float* sg = s_st + (t & 1) * 8192;
                const float* sgtx = sg + tx * 2;   // lane column base (tx*8 bytes)
#pragma unroll
                for (int rr = 0; rr < 8; rr++) {
                    int r = r0p + rr;
                    int n = s_nn[r];
                    const float2* cl = s_cl + r * 34;
                    for (int i = 0; i < n; i += 2) {
                        float4 p = *reinterpret_cast<const float4*>(cl + i);
                        {
                            unsigned long long a2 = pk2(p.x, p.x);
                            const unsigned long long* gp =
                                reinterpret_cast<const unsigned long long*>(
                                    sgtx + __float_as_int(p.y));
                            fma2(acc[rr][0], a2, gp[0]);
                            fma2(acc[rr][1], a2, gp[32]);
                            fma2(acc[rr][2], a2, gp[64]);
                            fma2(acc[rr][3], a2, gp[96]);
                        }
                        {
                            unsigned long long a2 = pk2(p.z, p.z);
                            const unsigned long long* gp =
                                reinterpret_cast<const unsigned long long*>(
                                    sgtx + __float_as_int(p.w));
                            fma2(acc[rr][0], a2, gp[0]);
                            fma2(acc[rr][1], a2, gp[32]);
                            fma2(acc[rr][2], a2, gp[64]);
                            fma2(acc[rr][3], a2, gp[96]);
                        }
                    }
                }
                __syncthreads();   // staging slot free for next prefetch
            }
        }

        // ---- speculative convergence decision: consume verdict for it-1 ----
        if (it > 0) {
            if (tid == 0) {
                unsigned target = (unsigned)NCTA * (unsigned)it;
                while (*((volatile unsigned*)&g_cnt) < target) __nanosleep(32);
                __threadfence();
            }
            __syncthreads();
            if (ty == 0) {
                volatile float* p = (volatile float*)g_part[(it - 1) & 1];
                float v = p[tx] + p[tx + 32] + p[tx + 64] + p[tx + 96];
#pragma unroll
                for (int o = 16; o > 0; o >>= 1) v += __shfl_xor_sync(0xffffffffu, v, o);
                if (tx == 0) s_red[32] = v;
            }
            __syncthreads();
            if (s_red[32] < TOLSQ) break;   // discard speculative acc
        }

        // epilogue: du = ex - u - acc ; u += LR*du ; accumulate du^2
        float lsum = 0.f;
#pragma unroll
        for (int ri = 0; ri < 8; ri++) {
            int rb = (r0p + ri) * NF;
#pragma unroll
            for (int ci = 0; ci < 4; ci++) {
                int base = rb + (tx + 32 * ci) * 2;
                float lo, hi; upk2(acc[ri][ci], lo, hi);
                float2 e = *reinterpret_cast<float2*>(s_ex + base);
                float2 u = *reinterpret_cast<float2*>(s_u + base);
                float d0 = e.x - u.x - lo;
                float d1 = e.y - u.y - hi;
                u.x += LRATE * d0;
                u.y += LRATE * d1;
                *reinterpret_cast<float2*>(s_u + base) = u;
                lsum += d0 * d0 + d1 * d1;
            }
        }
        // CTA-deterministic reduction of ||du||^2, post partial (NO wait here)
#pragma unroll
        for (int o = 16; o > 0; o >>= 1) lsum += __shfl_xor_sync(0xffffffffu, lsum, o);
        if (tx == 0) s_red[ty] = lsum;
        __syncthreads();   // also orders this iteration's s_u writes before next build
        if (tid == 0) {
            float c = 0.f;
#pragma unroll
            for (int w = 0; w < 8; w++) c += s_red[w];
            *((volatile float*)&g_part[it & 1][cta]) = c;
            __threadfence();
            atomicAdd(&g_cnt, 1u);
        }
        // no trailing sync: the next sync inside the tile loop re-converges tid 0
    }

    // output = threshold(u) (each thread reads back elements it owns)
#pragma unroll
    for (int ri = 0; ri < 8; ri++) {
        int rb = (r0p + ri) * NF;
#pragma unroll
        for (int ci = 0; ci < 4; ci++) {
            int base = rb + (tx + 32 * ci) * 2;
            float2 u = *reinterpret_cast<float2*>(s_u + base);
            u.x = (u.x > SHRINKV) ? u.x : 0.f;
            u.y = (u.y > SHRINKV) ? u.y : 0.f;
            *reinterpret_cast<float2*>(out + (size_t)(row0 + r0p + ri) * NF
                                       + (tx + 32 * ci) * 2) = u;
        }
    }
}

// ---------------- host launch ----------------
extern "C" void kernel_launch(void* const* d_in, const int* in_sizes, int n_in,
                              void* d_out, int out_size) {
    const float* images;
    const float* phi;
    if (in_sizes[0] == NB * KD) {
        images = (const float*)d_in[0];
        phi    = (const float*)d_in[1];
    } else {
        images = (const float*)d_in[1];
        phi    = (const float*)d_in[0];
    }
    float* out = (float*)d_out;

    cudaFuncSetAttribute(lca_kernel, cudaFuncAttributeMaxDynamicSharedMemorySize, 196608);

    init_kernel<<<1, 32>>>();
    gram_kernel<<<dim3(16, 16), 256>>>(phi);
    lca_kernel<<<NCTA, NTHR, 196608>>>(images, phi, out);
}

// round 17
// speedup vs baseline: 2.6328x; 2.6328x over previous
#include <cuda_runtime.h>
#include <cstdint>

#define NB 8192
#define KD 4096
#define NF 256
#define RPC 64          // rows per CTA
#define NCTA (NB/RPC)   // 128
#define NTHR 256
#define MAXIT 500
#define TOLSQ 1e-4f     // (0.01)^2
#define LRATE 0.1f
#define SHRINKV 0.25f

// ---------------- device scratch (no allocs allowed) ----------------
__device__ float g_G[NF * NF];          // Gram matrix, diag zeroed
__device__ float g_part[16][NCTA];      // per-CTA partial du^2, 16-deep ring
__device__ unsigned g_cnt;              // monotonic barrier counter

// ---------------- helpers ----------------
__device__ __forceinline__ unsigned long long pk2(float lo, float hi) {
    unsigned long long r;
    asm("mov.b64 %0, {%1, %2};" : "=l"(r) : "f"(lo), "f"(hi));
    return r;
}
__device__ __forceinline__ void upk2(unsigned long long v, float& lo, float& hi) {
    asm("mov.b64 {%0, %1}, %2;" : "=f"(lo), "=f"(hi) : "l"(v));
}
// packed fp32x2 FMA: d = a*b + d (full-rate fp32 path on sm_103a)
__device__ __forceinline__ void fma2(unsigned long long& d, unsigned long long a, unsigned long long b) {
    asm("fma.rn.f32x2 %0, %1, %2, %0;" : "+l"(d) : "l"(a), "l"(b));
}
__device__ __forceinline__ uint32_t s2u(const void* p) {
    return (uint32_t)__cvta_generic_to_shared(p);
}
__device__ __forceinline__ void cpasync16(uint32_t saddr, const void* g) {
    asm volatile("cp.async.cg.shared.global [%0], [%1], 16;" :: "r"(saddr), "l"(g));
}
#define CP_COMMIT() asm volatile("cp.async.commit_group;")

// ---------------- init: reset barrier counter (every replay) ----------------
__global__ void init_kernel() {
    if (threadIdx.x == 0) g_cnt = 0u;
}

// ---------------- Gram: G = phi^T phi, zero diagonal ----------------
__global__ void gram_kernel(const float* __restrict__ phi) {
    __shared__ float si[64][17];
    __shared__ float sj[64][17];
    const int I0 = blockIdx.y * 16, J0 = blockIdx.x * 16;
    const int t = threadIdx.x;
    const int ti = t & 15, tj = t >> 4;
    float acc = 0.f;
    for (int k0 = 0; k0 < KD; k0 += 64) {
        __syncthreads();
#pragma unroll
        for (int p = 0; p < 4; p++) {
            int kk = p * 16 + tj;
            si[kk][ti] = phi[(size_t)(k0 + kk) * NF + I0 + ti];
            sj[kk][ti] = phi[(size_t)(k0 + kk) * NF + J0 + ti];
        }
        __syncthreads();
#pragma unroll 16
        for (int kk = 0; kk < 64; kk++) acc += si[kk][tj] * sj[kk][ti];
    }
    const int gi = I0 + tj, gj = J0 + ti;
    g_G[gi * NF + gj] = (gi == gj) ? 0.f : acc;
}

// ---------------- persistent LCA kernel ----------------
// 128 CTAs x 256 threads, 1 CTA/SM (all resident -> spins are safe).
// Column mapping (conflict-free): thread (tx,ty) owns packed fp32-pairs
//   pc = tx + 32*ci (ci=0..3), i.e. float cols 2*pc, 2*pc+1.
// Convergence: each CTA posts its ||du||^2 partial every iteration (no wait).
// A CTA consults the GLOBAL verdict only when its OWN partial < TOLSQ
// (own <= total, so own >= TOLSQ proves "continue"). At the true stop
// iteration every partial < TOLSQ, so all CTAs check and break together ->
// decision sequence identical to the always-check version. 16-deep ring +
// an every-8-iteration loose back-pressure spin bounds CTA skew < 16.
// smem (dynamic 192KB): u[64][256] | excite[64][256] | staging 16384 floats
__global__ void __launch_bounds__(NTHR, 1)
lca_kernel(const float* __restrict__ images, const float* __restrict__ phi,
           float* __restrict__ out) {
    extern __shared__ float sm[];
    float* s_u  = sm;                 // 16384 floats
    float* s_ex = sm + RPC * NF;      // 16384 floats
    float* s_st = sm + 2 * RPC * NF;  // 16384 floats staging (G tiles / prologue tiles)
    __shared__ float s_at[RPC * 32];  // thresholded activation tile (64 x 32)
    __shared__ float s_red[40];       // [0..7] warp partials, [32] verdict, [33] own partial

    const int tid = threadIdx.x;
    const int tx = tid & 31, ty = tid >> 5;
    const int r0p = ty * 8;       // 8 rows per thread
    const int cta = blockIdx.x;
    const int row0 = cta * RPC;

    unsigned long long acc[8][4];

    // ================= prologue: excite = images[rows] @ phi =================
    {
        float* s_img = s_st;          // [64][16]
        float* s_phi = s_st + 1024;   // [16][256]
#pragma unroll
        for (int ri = 0; ri < 8; ri++)
#pragma unroll
            for (int ci = 0; ci < 4; ci++) acc[ri][ci] = 0ull;

        for (int kt = 0; kt < KD; kt += 16) {
            __syncthreads();
            {   // img tile 64x16
                int r = tid >> 2, c = (tid & 3) * 4;
                *reinterpret_cast<float4*>(s_img + r * 16 + c) =
                    *reinterpret_cast<const float4*>(images + (size_t)(row0 + r) * KD + kt + c);
            }
            {   // phi tile 16x256 = 4096 contiguous floats
                const float* src = phi + (size_t)kt * NF;
#pragma unroll
                for (int i = 0; i < 4; i++) {
                    int off = i * 1024 + tid * 4;
                    *reinterpret_cast<float4*>(s_phi + off) =
                        *reinterpret_cast<const float4*>(src + off);
                }
            }
            __syncthreads();
#pragma unroll
            for (int kp = 0; kp < 8; kp++) {   // 2 kk per step
                float2 ap[8];
#pragma unroll
                for (int ri = 0; ri < 8; ri++)
                    ap[ri] = *reinterpret_cast<const float2*>(
                        s_img + (r0p + ri) * 16 + kp * 2);
                const unsigned long long* gp0 =
                    reinterpret_cast<const unsigned long long*>(s_phi + (2 * kp) * NF);
                const unsigned long long* gp1 =
                    reinterpret_cast<const unsigned long long*>(s_phi + (2 * kp + 1) * NF);
#pragma unroll
                for (int ri = 0; ri < 8; ri++) {
                    unsigned long long a2 = pk2(ap[ri].x, ap[ri].x);
                    fma2(acc[ri][0], a2, gp0[tx]);
                    fma2(acc[ri][1], a2, gp0[tx + 32]);
                    fma2(acc[ri][2], a2, gp0[tx + 64]);
                    fma2(acc[ri][3], a2, gp0[tx + 96]);
                }
#pragma unroll
                for (int ri = 0; ri < 8; ri++) {
                    unsigned long long a2 = pk2(ap[ri].y, ap[ri].y);
                    fma2(acc[ri][0], a2, gp1[tx]);
                    fma2(acc[ri][1], a2, gp1[tx + 32]);
                    fma2(acc[ri][2], a2, gp1[tx + 64]);
                    fma2(acc[ri][3], a2, gp1[tx + 96]);
                }
            }
        }
        __syncthreads();
#pragma unroll
        for (int ri = 0; ri < 8; ri++)
#pragma unroll
            for (int ci = 0; ci < 4; ci++) {
                float lo, hi; upk2(acc[ri][ci], lo, hi);
                int base = (r0p + ri) * NF + (tx + 32 * ci) * 2;
                s_ex[base] = lo; s_ex[base + 1] = hi;
            }
        for (int i = tid; i < RPC * NF; i += NTHR) s_u[i] = 0.f;
        __syncthreads();
    }

    // ================= fixed-point iterations =================
    for (int it = 0; it < MAXIT; ++it) {
#pragma unroll
        for (int ri = 0; ri < 8; ri++)
#pragma unroll
            for (int ci = 0; ci < 4; ci++) acc[ri][ci] = 0ull;

        if (it > 0) {   // it==0: act==T(0)==0 -> acc stays 0, skip the GEMM
            // prefetch G tile 0 (32 rows x 256 cols, 32KB)
            {
                uint32_t dst = s2u(s_st);
                const float* src = g_G;
#pragma unroll
                for (int i = 0; i < 8; i++) {
                    int off = i * 1024 + tid * 4;
                    cpasync16(dst + off * 4, src + off);
                }
                CP_COMMIT();
            }

            for (int t = 0; t < 8; t++) {
                // build thresholded a-tile for k in [t*32, t*32+32)
                {
                    int r = tid >> 2, c = (tid & 3) * 8;
                    int kt = t * 32;
#pragma unroll
                    for (int h = 0; h < 2; h++) {
                        float4 v = *reinterpret_cast<float4*>(s_u + r * NF + kt + c + h * 4);
                        v.x = (v.x > SHRINKV) ? v.x : 0.f;
                        v.y = (v.y > SHRINKV) ? v.y : 0.f;
                        v.z = (v.z > SHRINKV) ? v.z : 0.f;
                        v.w = (v.w > SHRINKV) ? v.w : 0.f;
                        *reinterpret_cast<float4*>(s_at + r * 32 + c + h * 4) = v;
                    }
                }
                if (t < 7) {
                    uint32_t dst = s2u(s_st + ((t + 1) & 1) * 8192);
                    const float* src = g_G + (t + 1) * 8192;
#pragma unroll
                    for (int i = 0; i < 8; i++) {
                        int off = i * 1024 + tid * 4;
                        cpasync16(dst + off * 4, src + off);
                    }
                    CP_COMMIT();
                    asm volatile("cp.async.wait_group 1;");
                } else {
                    asm volatile("cp.async.wait_group 0;");
                }
                __syncthreads();

                const float* sg = s_st + (t & 1) * 8192;
#pragma unroll 2
                for (int kp = 0; kp < 16; kp++) {   // 2 kk per step
                    float2 ap[8];
#pragma unroll
                    for (int ri = 0; ri < 8; ri++)
                        ap[ri] = *reinterpret_cast<const float2*>(
                            s_at + (r0p + ri) * 32 + kp * 2);
                    const unsigned long long* gp0 =
                        reinterpret_cast<const unsigned long long*>(sg + (2 * kp) * NF);
                    const unsigned long long* gp1 =
                        reinterpret_cast<const unsigned long long*>(sg + (2 * kp + 1) * NF);
#pragma unroll
                    for (int ri = 0; ri < 8; ri++) {
                        unsigned long long a2 = pk2(ap[ri].x, ap[ri].x);
                        fma2(acc[ri][0], a2, gp0[tx]);
                        fma2(acc[ri][1], a2, gp0[tx + 32]);
                        fma2(acc[ri][2], a2, gp0[tx + 64]);
                        fma2(acc[ri][3], a2, gp0[tx + 96]);
                    }
#pragma unroll
                    for (int ri = 0; ri < 8; ri++) {
                        unsigned long long a2 = pk2(ap[ri].y, ap[ri].y);
                        fma2(acc[ri][0], a2, gp1[tx]);
                        fma2(acc[ri][1], a2, gp1[tx + 32]);
                        fma2(acc[ri][2], a2, gp1[tx + 64]);
                        fma2(acc[ri][3], a2, gp1[tx + 96]);
                    }
                }
                __syncthreads();
            }
        }

        // ---- convergence decision for it-1 (checked only when necessary) ----
        if (it > 0) {
            // own partial for it-1 (same value for every thread; written by
            // tid0 in epilogue it-1, ordered by the GEMM's syncthreads above)
            if (s_red[33] < TOLSQ) {
                if (tid == 0) {
                    unsigned target = (unsigned)NCTA * (unsigned)it;
                    while (*((volatile unsigned*)&g_cnt) < target) __nanosleep(32);
                    __threadfence();
                }
                __syncthreads();
                if (ty == 0) {
                    volatile float* p = (volatile float*)g_part[(it - 1) & 15];
                    float v = p[tx] + p[tx + 32] + p[tx + 64] + p[tx + 96];
#pragma unroll
                    for (int o = 16; o > 0; o >>= 1) v += __shfl_xor_sync(0xffffffffu, v, o);
                    if (tx == 0) s_red[32] = v;
                }
                __syncthreads();
                if (s_red[32] < TOLSQ) break;   // discard speculative acc
            }
            // loose back-pressure: bound CTA skew below the ring depth
            if ((it & 7) == 0 && it >= 8) {
                if (tid == 0) {
                    unsigned target = (unsigned)NCTA * (unsigned)(it - 7);
                    while (*((volatile unsigned*)&g_cnt) < target) __nanosleep(32);
                }
                __syncthreads();
            }
        }

        // epilogue: du = ex - u - acc ; u += LR*du ; accumulate du^2
        float lsum = 0.f;
#pragma unroll
        for (int ri = 0; ri < 8; ri++) {
            int rb = (r0p + ri) * NF;
#pragma unroll
            for (int ci = 0; ci < 4; ci++) {
                int base = rb + (tx + 32 * ci) * 2;
                float lo, hi; upk2(acc[ri][ci], lo, hi);
                float2 e = *reinterpret_cast<float2*>(s_ex + base);
                float2 u = *reinterpret_cast<float2*>(s_u + base);
                float d0 = e.x - u.x - lo;
                float d1 = e.y - u.y - hi;
                u.x += LRATE * d0;
                u.y += LRATE * d1;
                *reinterpret_cast<float2*>(s_u + base) = u;
                lsum += d0 * d0 + d1 * d1;
            }
        }
        // CTA-deterministic reduction of ||du||^2, post partial (NO wait here)
#pragma unroll
        for (int o = 16; o > 0; o >>= 1) lsum += __shfl_xor_sync(0xffffffffu, lsum, o);
        if (tx == 0) s_red[ty] = lsum;
        __syncthreads();   // also orders this iteration's s_u writes before next a-build
        if (tid == 0) {
            float c = 0.f;
#pragma unroll
            for (int w = 0; w < 8; w++) c += s_red[w];
            s_red[33] = c;   // own partial for the next iteration's check
            *((volatile float*)&g_part[it & 15][cta]) = c;
            __threadfence();
            atomicAdd(&g_cnt, 1u);
        }
        // no trailing sync: the next sync inside the tile loop re-converges tid 0
        // and orders s_red[33] before its consumers
    }

    // output = threshold(u) (each thread reads back elements it owns)
#pragma unroll
    for (int ri = 0; ri < 8; ri++) {
        int rb = (r0p + ri) * NF;
#pragma unroll
        for (int ci = 0; ci < 4; ci++) {
            int base = rb + (tx + 32 * ci) * 2;
            float2 u = *reinterpret_cast<float2*>(s_u + base);
            u.x = (u.x > SHRINKV) ? u.x : 0.f;
            u.y = (u.y > SHRINKV) ? u.y : 0.f;
            *reinterpret_cast<float2*>(out + (size_t)(row0 + r0p + ri) * NF
                                       + (tx + 32 * ci) * 2) = u;
        }
    }
}

// ---------------- host launch ----------------
extern "C" void kernel_launch(void* const* d_in, const int* in_sizes, int n_in,
                              void* d_out, int out_size) {
    const float* images;
    const float* phi;
    if (in_sizes[0] == NB * KD) {
        images = (const float*)d_in[0];
        phi    = (const float*)d_in[1];
    } else {
        images = (const float*)d_in[1];
        phi    = (const float*)d_in[0];
    }
    float* out = (float*)d_out;

    cudaFuncSetAttribute(lca_kernel, cudaFuncAttributeMaxDynamicSharedMemorySize, 196608);

    init_kernel<<<1, 32>>>();
    gram_kernel<<<dim3(16, 16), 256>>>(phi);
    lca_kernel<<<NCTA, NTHR, 196608>>>(images, phi, out);
}